// round 1
// baseline (speedup 1.0000x reference)
#include <cuda_runtime.h>
#include <cstdint>

// Problem constants (fixed by setup_inputs)
#define B_   8
#define C_   64
#define H_   128
#define W_   512
#define SATW 512
#define HALF 256
#define NPIX (B_*H_*W_)        // 524288
#define CELLS (B_*SATW*SATW)   // 2097152

__device__ float               g_kinv[B_*9];
__device__ unsigned int        g_maxy_ord;
__device__ unsigned long long  g_cellkey[CELLS];   // 16 MB scratch
__device__ int                 g_winner[CELLS];    //  8 MB scratch

// Monotonic float -> uint mapping (order preserving)
__device__ __forceinline__ unsigned int ford(float f) {
    unsigned int u = __float_as_uint(f);
    return (u & 0x80000000u) ? ~u : (u | 0x80000000u);
}
__device__ __forceinline__ float ford_inv(unsigned int o) {
    unsigned int u = (o & 0x80000000u) ? (o & 0x7FFFFFFFu) : ~o;
    return __uint_as_float(u);
}

// ---------------------------------------------------------------------------
// K0a: per-batch scaled-K inverse (adjugate; single-rounded divisions match
// the LU-based reference for this matrix structure) + reset global max.
// ---------------------------------------------------------------------------
__global__ void k_prep(const float* __restrict__ ck) {
    int b = threadIdx.x;
    if (b == 0) g_maxy_ord = 0u;
    if (b < B_) {
        const float rs0 = (float)W_ / 1024.0f;   // W / ori_grdW
        const float rs1 = (float)H_ / 256.0f;    // H / ori_grdH
        float a[9];
        #pragma unroll
        for (int r = 0; r < 3; r++) {
            float s = (r == 0) ? rs0 : (r == 1) ? rs1 : 1.0f;
            #pragma unroll
            for (int cc = 0; cc < 3; cc++)
                a[r*3+cc] = __fmul_rn(ck[b*9 + r*3 + cc], s);
        }
        float c00 = a[4]*a[8] - a[5]*a[7];
        float c01 = a[5]*a[6] - a[3]*a[8];
        float c02 = a[3]*a[7] - a[4]*a[6];
        float det = a[0]*c00 + a[1]*c01 + a[2]*c02;
        float inv[9];
        inv[0] = __fdiv_rn(c00, det);
        inv[1] = __fdiv_rn(a[2]*a[7] - a[1]*a[8], det);
        inv[2] = __fdiv_rn(a[1]*a[5] - a[2]*a[4], det);
        inv[3] = __fdiv_rn(c01, det);
        inv[4] = __fdiv_rn(a[0]*a[8] - a[2]*a[6], det);
        inv[5] = __fdiv_rn(a[2]*a[3] - a[0]*a[5], det);
        inv[6] = __fdiv_rn(c02, det);
        inv[7] = __fdiv_rn(a[1]*a[6] - a[0]*a[7], det);
        inv[8] = __fdiv_rn(a[0]*a[4] - a[1]*a[3], det);
        #pragma unroll
        for (int i = 0; i < 9; i++) g_kinv[b*9 + i] = inv[i];
    }
}

// ---------------------------------------------------------------------------
// K0b: reset the per-cell packed keys (re-run every graph replay)
// ---------------------------------------------------------------------------
__global__ void k_initcells() {
    int i = blockIdx.x * blockDim.x + threadIdx.x;
    if (i < CELLS) g_cellkey[i] = 0ull;
}

// ---------------------------------------------------------------------------
// Shared per-point geometry (exact op order vs reference; no fma contraction)
// ---------------------------------------------------------------------------
struct Pt { int x, z; float y; bool kept; };

__device__ __forceinline__ Pt compute_pt(int i, const float* __restrict__ depth,
                                         float mpp) {
    int b   = i >> 16;           // H*W = 65536
    int pix = i & 0xFFFF;
    float v = (float)(pix >> 9); // W = 512
    float u = (float)(pix & 511);
    const float* K = &g_kinv[b*9];
    float xw = __fadd_rn(__fadd_rn(__fmul_rn(K[0], u), __fmul_rn(K[1], v)), K[2]);
    float yw = __fadd_rn(__fadd_rn(__fmul_rn(K[3], u), __fmul_rn(K[4], v)), K[5]);
    float zw = __fadd_rn(__fadd_rn(__fmul_rn(K[6], u), __fmul_rn(K[7], v)), K[8]);
    float d  = __ldg(depth + i);
    float X  = __fmul_rn(__fmul_rn(xw, d), 1.2f);
    float Y  = __fmul_rn(__fmul_rn(yw, d), 1.2f);
    float Z  = __fmul_rn(__fmul_rn(zw, d), 1.2f);
    int xi = (int)__fdiv_rn(X, mpp);   // trunc toward zero == jnp.trunc + int32
    int zi = (int)__fdiv_rn(Z, mpp);
    Pt p;
    p.x = xi; p.z = zi; p.y = Y;
    p.kept = (xi >= -HALF) && (xi <= HALF-1) && (zi >= -HALF) && (zi <= HALF-1);
    return p;
}

// ---------------------------------------------------------------------------
// K1: global max of y over kept points
// ---------------------------------------------------------------------------
__global__ void k_maxy(const float* __restrict__ depth,
                       const float* __restrict__ mpp_p) {
    int i = blockIdx.x * blockDim.x + threadIdx.x;
    unsigned int o = 0u;
    if (i < NPIX) {
        Pt p = compute_pt(i, depth, __ldg(mpp_p));
        if (p.kept) o = ford(p.y);
    }
    o = __reduce_max_sync(0xFFFFFFFFu, o);
    if ((threadIdx.x & 31) == 0 && o != 0u) atomicMax(&g_maxy_ord, o);
}

// ---------------------------------------------------------------------------
// K2: per-point atomicMax of packed key (ordered(h)<<16 | pixel_index).
// Reproduces lexsort((h, rank)) + is_last selection exactly, including
// fp32 ties in h (tie -> larger original index wins).
// ---------------------------------------------------------------------------
__global__ void k_scatter(const float* __restrict__ depth,
                          const float* __restrict__ mpp_p) {
    int i = blockIdx.x * blockDim.x + threadIdx.x;
    if (i >= NPIX) return;
    Pt p = compute_pt(i, depth, __ldg(mpp_p));
    if (!p.kept) return;
    float max_h = ford_inv(g_maxy_ord);
    float h = __fadd_rn(max_h, -p.y);          // rn(max_h - y)
    int b   = i >> 16;
    int pix = i & 0xFFFF;
    unsigned long long key =
        ((unsigned long long)ford(h) << 16) | (unsigned long long)pix;
    int xx = p.x + HALF, zz = p.z + HALF;
    int cell = ((b * SATW) + xx) * SATW + zz;
    atomicMax(&g_cellkey[cell], key);
}

// ---------------------------------------------------------------------------
// K3: decode winners to compact int32 (-1 = empty)
// ---------------------------------------------------------------------------
__global__ void k_winner() {
    int i = blockIdx.x * blockDim.x + threadIdx.x;
    if (i < CELLS) {
        unsigned long long k = g_cellkey[i];
        g_winner[i] = k ? (int)(k & 0xFFFFull) : -1;
    }
}

// ---------------------------------------------------------------------------
// K4: big output pass — 536 MB streaming write + per-plane feature gather.
// out[b,c,xx,zz] = winner ? image[b,c,pix] : 0. float4 over zz.
// ---------------------------------------------------------------------------
__global__ void k_out(const float* __restrict__ image,
                      float4* __restrict__ out) {
    int idx = blockIdx.x * blockDim.x + threadIdx.x;   // 0 .. 33554431
    int zz4 = idx & 127;
    int t   = idx >> 7;
    int xx  = t & 511;
    t >>= 9;
    int c   = t & 63;
    int b   = t >> 6;

    const int4 w = __ldg(reinterpret_cast<const int4*>(
        &g_winner[(((b << 9) + xx) << 9) + (zz4 << 2)]));
    const float* plane = image + ((size_t)((b << 6) + c) << 16);  // H*W = 65536

    float4 o;
    o.x = (w.x >= 0) ? __ldg(plane + w.x) : 0.0f;
    o.y = (w.y >= 0) ? __ldg(plane + w.y) : 0.0f;
    o.z = (w.z >= 0) ? __ldg(plane + w.z) : 0.0f;
    o.w = (w.w >= 0) ? __ldg(plane + w.w) : 0.0f;
    __stcs(&out[idx], o);   // streaming: don't pollute L2 with the 536MB write
}

// ---------------------------------------------------------------------------
extern "C" void kernel_launch(void* const* d_in, const int* in_sizes, int n_in,
                              void* d_out, int out_size) {
    const float* image = (const float*)d_in[0];   // (B,C,H,W) f32
    const float* ck    = (const float*)d_in[1];   // (B,3,3)   f32
    const float* depth = (const float*)d_in[2];   // (B,H,W)   f32
    const float* mpp   = (const float*)d_in[3];   // (1,)      f32
    float* out = (float*)d_out;

    k_prep<<<1, 32>>>(ck);
    k_initcells<<<CELLS / 256, 256>>>();
    k_maxy<<<NPIX / 256, 256>>>(depth, mpp);
    k_scatter<<<NPIX / 256, 256>>>(depth, mpp);
    k_winner<<<CELLS / 256, 256>>>();
    k_out<<<(B_ * C_ * SATW * SATW / 4) / 256, 256>>>(image, (float4*)out);
    (void)in_sizes; (void)n_in; (void)out_size;
}